// round 4
// baseline (speedup 1.0000x reference)
#include <cuda_runtime.h>
#include <cstdint>

// ---------------------------------------------------------------------------
// MultiHeadAttention: B=2, S=2048, D=1024, H=16, d_k=64
// Inputs (metadata order): query,key,value [2,2048,1024] f32;
//   Wq,bq,Wk,bk,Wv,bv,Wo,bo
// Output: concat( output [2,2048,1024], attention_weights [2,16,2048,2048] )
// Round 4: audited fp32 SIMT baseline (resubmission — 4x broker timeout).
// QKV projections batched into ONE launch (blockIdx.z selects the problem).
// GEMM double-buffered. Fused attention writes the 537MB weights once.
// ---------------------------------------------------------------------------

#define B_SZ    2
#define S_LEN   2048
#define D_MODEL 1024
#define NH      16
#define DK      64

#define MROWS   (B_SZ * S_LEN)            // 4096

// scratch: Q, K, V, Ctx each 4096x1024 f32
__device__ float g_scratch[4u * MROWS * D_MODEL];

// ===================== GEMM core  C = A*B + bias ===========================
// A [M x 1024] row-major, B [1024 x 1024] row-major, bias [1024], C [M x 1024]
// 128x128 CTA tile, BK=8, 256 threads, 8x8 per thread, float4, double-buffered.
__device__ __forceinline__
void gemm_tile_128(const float* __restrict__ A, const float* __restrict__ B,
                   const float* __restrict__ bias, float* __restrict__ C,
                   int N, int Kd, int cRow, int cCol,
                   float (*As)[8][128], float (*Bs)[8][128])
{
    const int tid  = threadIdx.x;

    const int aRow = tid >> 1;            // 0..127
    const int aCol = (tid & 1) << 2;      // 0 or 4
    const int bRow = tid >> 5;            // 0..7
    const int bCol = (tid & 31) << 2;     // 0..124

    const float* Ab = A + (size_t)cRow * 128 * Kd;
    const float* Bb = B + (size_t)cCol * 128;

    const int tr = (tid >> 4) << 3;       // thread row base in tile
    const int tc = (tid & 15) << 3;       // thread col base in tile

    float acc[8][8];
#pragma unroll
    for (int i = 0; i < 8; i++)
#pragma unroll
        for (int j = 0; j < 8; j++) acc[i][j] = 0.f;

    // prologue: fill buffer 0
    {
        float4 a4 = *reinterpret_cast<const float4*>(&Ab[(size_t)aRow * Kd + aCol]);
        As[0][aCol + 0][aRow] = a4.x;
        As[0][aCol + 1][aRow] = a4.y;
        As[0][aCol + 2][aRow] = a4.z;
        As[0][aCol + 3][aRow] = a4.w;
        float4 b4 = *reinterpret_cast<const float4*>(&Bb[(size_t)bRow * N + bCol]);
        *reinterpret_cast<float4*>(&Bs[0][bRow][bCol]) = b4;
    }
    __syncthreads();

    int buf = 0;
    for (int k0 = 0; k0 < Kd; k0 += 8) {
        const bool has_next = (k0 + 8) < Kd;
        float4 an, bn;
        if (has_next) {     // issue global loads early; consume after compute
            an = *reinterpret_cast<const float4*>(&Ab[(size_t)aRow * Kd + k0 + 8 + aCol]);
            bn = *reinterpret_cast<const float4*>(&Bb[(size_t)(k0 + 8 + bRow) * N + bCol]);
        }

#pragma unroll
        for (int k = 0; k < 8; k++) {
            float ra[8], rb[8];
            *reinterpret_cast<float4*>(ra)     = *reinterpret_cast<const float4*>(&As[buf][k][tr]);
            *reinterpret_cast<float4*>(ra + 4) = *reinterpret_cast<const float4*>(&As[buf][k][tr + 4]);
            *reinterpret_cast<float4*>(rb)     = *reinterpret_cast<const float4*>(&Bs[buf][k][tc]);
            *reinterpret_cast<float4*>(rb + 4) = *reinterpret_cast<const float4*>(&Bs[buf][k][tc + 4]);
#pragma unroll
            for (int i = 0; i < 8; i++)
#pragma unroll
                for (int j = 0; j < 8; j++)
                    acc[i][j] += ra[i] * rb[j];
        }

        if (has_next) {
            int nb = buf ^ 1;
            As[nb][aCol + 0][aRow] = an.x;
            As[nb][aCol + 1][aRow] = an.y;
            As[nb][aCol + 2][aRow] = an.z;
            As[nb][aCol + 3][aRow] = an.w;
            *reinterpret_cast<float4*>(&Bs[nb][bRow][bCol]) = bn;
        }
        __syncthreads();
        buf ^= 1;
    }

    // epilogue: add bias, store float4
    const float* bb = bias + (size_t)cCol * 128 + tc;
    float rbias[8];
    *reinterpret_cast<float4*>(rbias)     = *reinterpret_cast<const float4*>(&bb[0]);
    *reinterpret_cast<float4*>(rbias + 4) = *reinterpret_cast<const float4*>(&bb[4]);
#pragma unroll
    for (int i = 0; i < 8; i++) {
        float* crow = C + (size_t)(cRow * 128 + tr + i) * N + cCol * 128 + tc;
        float4 o0, o1;
        o0.x = acc[i][0] + rbias[0]; o0.y = acc[i][1] + rbias[1];
        o0.z = acc[i][2] + rbias[2]; o0.w = acc[i][3] + rbias[3];
        o1.x = acc[i][4] + rbias[4]; o1.y = acc[i][5] + rbias[5];
        o1.z = acc[i][6] + rbias[6]; o1.w = acc[i][7] + rbias[7];
        *reinterpret_cast<float4*>(&crow[0]) = o0;
        *reinterpret_cast<float4*>(&crow[4]) = o1;
    }
}

// Batched QKV projection: blockIdx.z in {0,1,2} selects (input, W, bias, out).
__global__ __launch_bounds__(256)
void qkv_gemm(const float* __restrict__ q_in, const float* __restrict__ k_in,
              const float* __restrict__ v_in,
              const float* __restrict__ Wq, const float* __restrict__ bq,
              const float* __restrict__ Wk, const float* __restrict__ bk,
              const float* __restrict__ Wv, const float* __restrict__ bv,
              float* __restrict__ gQ, float* __restrict__ gK,
              float* __restrict__ gV)
{
    __shared__ float As[2][8][128];
    __shared__ float Bs[2][8][128];

    const float* A; const float* W; const float* bias; float* C;
    if (blockIdx.z == 0)      { A = q_in; W = Wq; bias = bq; C = gQ; }
    else if (blockIdx.z == 1) { A = k_in; W = Wk; bias = bk; C = gK; }
    else                      { A = v_in; W = Wv; bias = bv; C = gV; }

    gemm_tile_128(A, W, bias, C, D_MODEL, D_MODEL, blockIdx.y, blockIdx.x, As, Bs);
}

__global__ __launch_bounds__(256)
void sgemm_bias(const float* __restrict__ A, const float* __restrict__ B,
                const float* __restrict__ bias, float* __restrict__ C,
                int N, int Kd)
{
    __shared__ float As[2][8][128];
    __shared__ float Bs[2][8][128];
    gemm_tile_128(A, B, bias, C, N, Kd, blockIdx.y, blockIdx.x, As, Bs);
}

// ==================== fused attention per 16 query rows ====================
// grid: (S/16, NH, B), 512 threads.
// Phase 1: scores[16][2048] = Q K^T / 8 into smem (K streamed in 256-col chunks)
// Phase 2: row softmax (one warp per row), write weights to gmem + keep in smem
// Phase 3: context[16][64] = W V (V streamed, per-thread partial accumulators,
//          smem tree-reduce), written in merged-head [B,S,D] layout.

#define ROWS  16
#define CHUNK 256
#define KPAD  68        // 64 + 4 pad (16B aligned rows)
#define SPAD  2049      // odd row stride -> conflict-free column access

#define ATTN_SMEM_FLOATS (ROWS * SPAD + CHUNK * KPAD)

__global__ __launch_bounds__(512, 1)
void attn_fused(const float* __restrict__ Q, const float* __restrict__ K,
                const float* __restrict__ V, float* __restrict__ Wout,
                float* __restrict__ Ctx)
{
    extern __shared__ float sm[];
    float* s_sm = sm;                    // ROWS * SPAD
    float* k_sm = sm + ROWS * SPAD;      // CHUNK * KPAD (K chunk, later V chunk)

    const int tid = threadIdx.x;
    const int qb  = blockIdx.x;
    const int h   = blockIdx.y;
    const int b   = blockIdx.z;
    const int s0  = qb * ROWS;

    const size_t headoff = (size_t)b * S_LEN * D_MODEL + (size_t)h * DK;
    const float* Qh = Q + headoff;       // [s][d] stride D_MODEL
    const float* Kh = K + headoff;
    const float* Vh = V + headoff;

    const int row = tid & 15;            // 0..15  (query row within block)
    const int cg  = tid >> 4;            // 0..31  (column group)

    // ---- stage Q rows via smem, pull own row into registers ----
    {
        int l = tid * 2;                 // 1024 floats total
        int r = l >> 6, d = l & 63;
        float2 v2 = *reinterpret_cast<const float2*>(&Qh[(size_t)(s0 + r) * D_MODEL + d]);
        k_sm[r * KPAD + d]     = v2.x;
        k_sm[r * KPAD + d + 1] = v2.y;
    }
    __syncthreads();
    float qreg[64];
#pragma unroll
    for (int d = 0; d < 64; d++) qreg[d] = k_sm[row * KPAD + d];
    __syncthreads();

    // ---- Phase 1: scores ----
    for (int ci = 0; ci < S_LEN / CHUNK; ci++) {
#pragma unroll
        for (int it = 0; it < 8; it++) {             // 4096 float4 / 512 thr
            int l  = tid + it * 512;
            int c  = l >> 4;
            int d4 = (l & 15) << 2;
            float4 kv = *reinterpret_cast<const float4*>(
                &Kh[(size_t)(ci * CHUNK + c) * D_MODEL + d4]);
            *reinterpret_cast<float4*>(&k_sm[c * KPAD + d4]) = kv;
        }
        __syncthreads();
#pragma unroll
        for (int cc = 0; cc < CHUNK / 32; cc++) {
            int c = (cc << 5) + cg;
            const float4* kp = reinterpret_cast<const float4*>(&k_sm[c * KPAD]);
            float acc = 0.f;
#pragma unroll
            for (int d4 = 0; d4 < 16; d4++) {
                float4 kv = kp[d4];
                acc += qreg[4 * d4 + 0] * kv.x;
                acc += qreg[4 * d4 + 1] * kv.y;
                acc += qreg[4 * d4 + 2] * kv.z;
                acc += qreg[4 * d4 + 3] * kv.w;
            }
            s_sm[row * SPAD + ci * CHUNK + c] = acc * 0.125f;
        }
        __syncthreads();
    }

    // ---- Phase 2: softmax, one warp per row ----
    {
        const int wrow = tid >> 5;       // 0..15
        const int lane = tid & 31;
        float* srow = &s_sm[wrow * SPAD];

        float m = -1e30f;
#pragma unroll
        for (int j = 0; j < S_LEN / 32; j++) m = fmaxf(m, srow[lane + 32 * j]);
#pragma unroll
        for (int o = 16; o > 0; o >>= 1) m = fmaxf(m, __shfl_xor_sync(0xffffffffu, m, o));

        float z = 0.f;
#pragma unroll
        for (int j = 0; j < S_LEN / 32; j++) {
            float e = __expf(srow[lane + 32 * j] - m);
            srow[lane + 32 * j] = e;
            z += e;
        }
#pragma unroll
        for (int o = 16; o > 0; o >>= 1) z += __shfl_xor_sync(0xffffffffu, z, o);
        float invz = 1.f / z;

        float* wout = Wout + ((((size_t)b * NH + h) * S_LEN) + s0 + wrow) * S_LEN;
#pragma unroll
        for (int j = 0; j < S_LEN / 32; j++) {
            float wv = srow[lane + 32 * j] * invz;
            srow[lane + 32 * j] = wv;
            wout[lane + 32 * j] = wv;
        }
    }
    __syncthreads();

    // ---- Phase 3: PV ----
    float acc[64];
#pragma unroll
    for (int d = 0; d < 64; d++) acc[d] = 0.f;

    for (int ci = 0; ci < S_LEN / CHUNK; ci++) {
#pragma unroll
        for (int it = 0; it < 8; it++) {
            int l  = tid + it * 512;
            int c  = l >> 4;
            int d4 = (l & 15) << 2;
            float4 vv = *reinterpret_cast<const float4*>(
                &Vh[(size_t)(ci * CHUNK + c) * D_MODEL + d4]);
            *reinterpret_cast<float4*>(&k_sm[c * KPAD + d4]) = vv;
        }
        __syncthreads();
#pragma unroll
        for (int cc = 0; cc < CHUNK / 32; cc++) {
            int c = (cc << 5) + cg;
            float wv = s_sm[row * SPAD + ci * CHUNK + c];
            const float4* vp = reinterpret_cast<const float4*>(&k_sm[c * KPAD]);
#pragma unroll
            for (int d4 = 0; d4 < 16; d4++) {
                float4 vv = vp[d4];
                acc[4 * d4 + 0] += wv * vv.x;
                acc[4 * d4 + 1] += wv * vv.y;
                acc[4 * d4 + 2] += wv * vv.z;
                acc[4 * d4 + 3] += wv * vv.w;
            }
        }
        __syncthreads();
    }

    // ---- cross-thread reduction of 32 partials per row (reuse s_sm) ----
    float* sred = s_sm;                  // needs 512*64 = 32768 <= 16*2049
#pragma unroll
    for (int d = 0; d < 64; d++) sred[d * 512 + tid] = acc[d];
    __syncthreads();
    {
        int row_o = tid & 15;
        int d0    = (tid >> 4) << 1;     // 2 dims per thread
        float s0v = 0.f, s1v = 0.f;
#pragma unroll
        for (int g = 0; g < 32; g++) {
            s0v += sred[(d0 + 0) * 512 + g * 16 + row_o];
            s1v += sred[(d0 + 1) * 512 + g * 16 + row_o];
        }
        float2 o; o.x = s0v; o.y = s1v;
        *reinterpret_cast<float2*>(
            &Ctx[((size_t)b * S_LEN + s0 + row_o) * D_MODEL + h * DK + d0]) = o;
    }
}

// ============================== launch =====================================
extern "C" void kernel_launch(void* const* d_in, const int* in_sizes, int n_in,
                              void* d_out, int out_size)
{
    (void)in_sizes; (void)n_in; (void)out_size;

    const float* query = (const float*)d_in[0];
    const float* key   = (const float*)d_in[1];
    const float* value = (const float*)d_in[2];
    const float* Wq    = (const float*)d_in[3];
    const float* bq    = (const float*)d_in[4];
    const float* Wk    = (const float*)d_in[5];
    const float* bk    = (const float*)d_in[6];
    const float* Wv    = (const float*)d_in[7];
    const float* bv    = (const float*)d_in[8];
    const float* Wo    = (const float*)d_in[9];
    const float* bo    = (const float*)d_in[10];

    float* out  = (float*)d_out;                                   // [2,2048,1024]
    float* attw = out + (size_t)B_SZ * S_LEN * D_MODEL;            // [2,16,2048,2048]

    float* scratch = nullptr;
    cudaGetSymbolAddress((void**)&scratch, g_scratch);
    float* gQ = scratch;
    float* gK = scratch + 1u * MROWS * D_MODEL;
    float* gV = scratch + 2u * MROWS * D_MODEL;
    float* gC = scratch + 3u * MROWS * D_MODEL;

    const size_t attn_smem = (size_t)ATTN_SMEM_FLOATS * sizeof(float);
    cudaFuncSetAttribute(attn_fused, cudaFuncAttributeMaxDynamicSharedMemorySize,
                         (int)attn_smem);

    dim3 gg(D_MODEL / 128, MROWS / 128, 3);   // (8, 32, 3) = 768 CTAs
    qkv_gemm<<<gg, 256>>>(query, key, value, Wq, bq, Wk, bk, Wv, bv, gQ, gK, gV);

    attn_fused<<<dim3(S_LEN / ROWS, NH, B_SZ), 512, attn_smem>>>(gQ, gK, gV, attw, gC);

    sgemm_bias<<<dim3(D_MODEL / 128, MROWS / 128), 256>>>(gC, Wo, bo, out,
                                                          D_MODEL, D_MODEL);
}